// round 6
// baseline (speedup 1.0000x reference)
#include <cuda_runtime.h>
#include <math.h>

#define NN 50000
#define EE 800000
#define ET (EE + NN)   // edges + self loops
#define DIM 64
#define GG 256
#define CC 10
#define NEG_SLOPE 0.2f
#define NB ((NN + 255) / 256)   // scan blocks = 196

// ---------------- device scratch (static, no allocation) ----------------
__device__ float g_hA[NN * DIM];
__device__ float g_hB[NN * DIM];
__device__ float g_fin[NN * DIM];    // final normalized layer-3 output (head input)
__device__ float g_asA[NN], g_adA[NN];
__device__ float g_asB[NN], g_adB[NN];
__device__ int   g_is64;

// CSR (built once per launch, reused by all 3 layers)
__device__ int g_deg[NN];
__device__ int g_wcnt[NN];
__device__ int g_row[NN + 1];
__device__ int g_bsum[NB];
__device__ int g_esrc[ET];

// ---------------- helpers ----------------
__device__ __forceinline__ float wsum(float v) {
#pragma unroll
    for (int o = 16; o; o >>= 1) v += __shfl_xor_sync(0xffffffffu, v, o);
    return v;
}
__device__ __forceinline__ float wmax(float v) {
#pragma unroll
    for (int o = 16; o; o >>= 1) v = fmaxf(v, __shfl_xor_sync(0xffffffffu, v, o));
    return v;
}
__device__ __forceinline__ int iwsum(int v) {
#pragma unroll
    for (int o = 16; o; o >>= 1) v += __shfl_xor_sync(0xffffffffu, v, o);
    return v;
}

__device__ __forceinline__ void load_edge(const void* ei, int e, int& s, int& d) {
    if (e >= EE) { s = d = e - EE; return; }  // self loop
    if (g_is64) {
        const long long* p = (const long long*)ei;
        s = (int)p[e];
        d = (int)p[EE + e];
    } else {
        const int* p = (const int*)ei;
        s = p[e];
        d = p[EE + e];
    }
}

__device__ __forceinline__ long long load_batch(const void* batch, int n) {
    return g_is64 ? ((const long long*)batch)[n]
                  : (long long)((const int*)batch)[n];
}

// ---------------- K0: detect int64 vs int32 (1 warp) ----------------
__global__ void k_detect(const void* ei) {
    const int* p = (const int*)ei;
    int lane = threadIdx.x;
    int bad = (p[2 * lane + 1] != 0) | (p[2 * (lane + 32) + 1] != 0);
    unsigned any = __ballot_sync(0xffffffffu, bad);
    if (lane == 0) g_is64 = (any == 0u) ? 1 : 0;
}

// ---------------- CSR build ----------------
__global__ void k_hist(const void* __restrict__ ei) {
    int e = blockIdx.x * blockDim.x + threadIdx.x;
    if (e >= ET) return;
    int s, d;
    load_edge(ei, e, s, d);
    atomicAdd(&g_deg[d], 1);
}

__global__ void k_scan_block() {
    __shared__ int sm[256];
    int t = threadIdx.x;
    int i = blockIdx.x * 256 + t;
    int v = (i < NN) ? g_deg[i] : 0;
    sm[t] = v;
    __syncthreads();
#pragma unroll
    for (int off = 1; off < 256; off <<= 1) {
        int tmp = (t >= off) ? sm[t - off] : 0;
        __syncthreads();
        sm[t] += tmp;
        __syncthreads();
    }
    if (i < NN) g_row[i] = sm[t] - v;   // exclusive within block
    if (t == 255) g_bsum[blockIdx.x] = sm[255];
}

// merged scan_top + scan_add
__global__ void k_scan_fix() {
    __shared__ int wred[8];
    __shared__ int s_off;
    int t = threadIdx.x;
    int v = (t < blockIdx.x && t < NB) ? g_bsum[t] : 0;
    v = iwsum(v);
    if ((t & 31) == 0) wred[t >> 5] = v;
    __syncthreads();
    if (t == 0) {
        int o = 0;
#pragma unroll
        for (int k = 0; k < 8; k++) o += wred[k];
        s_off = o;
    }
    __syncthreads();
    int i = blockIdx.x * 256 + t;
    if (i < NN) g_row[i] += s_off;
    if (blockIdx.x == 0 && t == 0) g_row[NN] = ET;
}

__global__ void k_scatter(const void* __restrict__ ei) {
    int e = blockIdx.x * blockDim.x + threadIdx.x;
    if (e >= ET) return;
    int s, d;
    load_edge(ei, e, s, d);
    int pos = g_row[d] + atomicAdd(&g_wcnt[d], 1);
    g_esrc[pos] = s;
}

// ---------------- K1: h = xin @ W + attention scalars (layer 1 only) ----------------
__global__ __launch_bounds__(256) void k_gemm_attn(
        const float* __restrict__ xin, const float* __restrict__ w,
        const float* __restrict__ a_src, const float* __restrict__ a_dst,
        float* __restrict__ hout, float* __restrict__ asout, float* __restrict__ adout) {
    __shared__ float ws[DIM * DIM];          // 16 KB
    __shared__ float xr[32][DIM];            // 8 KB
    __shared__ float pr1a[32], pr1b[32], pr2a[32], pr2b[32];
    int tid = threadIdx.x;
    int base = blockIdx.x * 32;

    {
        const float4* w4 = (const float4*)w;
        float4* ws4 = (float4*)ws;
#pragma unroll
        for (int k = tid; k < DIM * DIM / 4; k += 256) ws4[k] = w4[k];
    }
    {
        const float4* x4 = (const float4*)xin;
        float4* xr4 = (float4*)&xr[0][0];
#pragma unroll
        for (int k = tid; k < 32 * DIM / 4; k += 256) {
            int row = k >> 4;
            float4 v = make_float4(0.f, 0.f, 0.f, 0.f);
            if (base + row < NN) v = x4[(long)(base + row) * 16 + (k & 15)];
            xr4[k] = v;
        }
    }
    __syncthreads();

    int t = tid & 63;
    int grp = tid >> 6;
    int wsel = (tid >> 5) & 1;
    float as_t = __ldg(&a_src[t]);
    float ad_t = __ldg(&a_dst[t]);

#pragma unroll
    for (int r = grp; r < 32; r += 4) {
        int i = base + r;
        float h = 0.0f;
#pragma unroll
        for (int k = 0; k < DIM; k++) h = fmaf(xr[r][k], ws[k * DIM + t], h);
        float r1 = wsum(h * as_t);
        float r2 = wsum(h * ad_t);
        if ((tid & 31) == 0) {
            if (wsel == 0) { pr1a[r] = r1; pr2a[r] = r2; }
            else           { pr1b[r] = r1; pr2b[r] = r2; }
        }
        if (i < NN) hout[i * DIM + t] = h;
    }
    __syncthreads();
    if (tid < 32 && base + tid < NN) {
        asout[base + tid] = pr1a[tid] + pr1b[tid];
        adout[base + tid] = pr2a[tid] + pr2b[tid];
    }
}

// ---------------- aggregation core (softmax + gather + bias + l2norm + relu) ----------
// returns normalized relu'd row: lanes sub==0 hold float4 chunk q (dims 4q..4q+3);
// duplicated in sub==1.
__device__ __forceinline__ float4 agg_core(
        int i, int lane, int sub, int q,
        const float* __restrict__ hin,
        const float* __restrict__ asin, float ad_i,
        const float* __restrict__ bias) {
    int beg = g_row[i];
    int end = g_row[i + 1];
    int deg = end - beg;
    const float4* h4 = (const float4*)hin;
    float4 acc = make_float4(0.f, 0.f, 0.f, 0.f);

    if (deg <= 32) {
        int s_l = 0;
        float e_l = -1e30f;
        if (lane < deg) {
            s_l = g_esrc[beg + lane];
            float v = asin[s_l] + ad_i;
            e_l = (v > 0.0f) ? v : NEG_SLOPE * v;
        }
        float emax = wmax(e_l);
        float ex = (lane < deg) ? __expf(e_l - emax) : 0.0f;
        float denom = wsum(ex) + 1e-16f;
        float alpha_l = ex / denom;
#pragma unroll 4
        for (int k = 0; k < deg; k += 2) {
            int kk = k + sub;
            float a = __shfl_sync(0xffffffffu, alpha_l, kk);
            int s = __shfl_sync(0xffffffffu, s_l, kk);
            float4 hv = __ldg(&h4[(long)s * 16 + q]);
            acc.x = fmaf(a, hv.x, acc.x);
            acc.y = fmaf(a, hv.y, acc.y);
            acc.z = fmaf(a, hv.z, acc.z);
            acc.w = fmaf(a, hv.w, acc.w);
        }
    } else {
        float emax = -1e30f;
        for (int j = beg + lane; j < end; j += 32) {
            int s = g_esrc[j];
            float v = asin[s] + ad_i;
            v = (v > 0.0f) ? v : NEG_SLOPE * v;
            emax = fmaxf(emax, v);
        }
        emax = wmax(emax);
        float dsum = 0.0f;
        for (int j = beg + lane; j < end; j += 32) {
            int s = g_esrc[j];
            float v = asin[s] + ad_i;
            v = (v > 0.0f) ? v : NEG_SLOPE * v;
            dsum += __expf(v - emax);
        }
        float denom = wsum(dsum) + 1e-16f;
        for (int cbase = beg; cbase < end; cbase += 32) {
            int j = cbase + lane;
            int s_l = 0;
            float alpha_l = 0.0f;
            if (j < end) {
                s_l = g_esrc[j];
                float v = asin[s_l] + ad_i;
                v = (v > 0.0f) ? v : NEG_SLOPE * v;
                alpha_l = __expf(v - emax) / denom;
            }
            int cnt = min(32, end - cbase);
#pragma unroll 4
            for (int k = 0; k < cnt; k += 2) {
                int kk = k + sub;
                float a = __shfl_sync(0xffffffffu, alpha_l, kk);
                int s = __shfl_sync(0xffffffffu, s_l, kk);
                float4 hv = __ldg(&h4[(long)s * 16 + q]);
                acc.x = fmaf(a, hv.x, acc.x);
                acc.y = fmaf(a, hv.y, acc.y);
                acc.z = fmaf(a, hv.z, acc.z);
                acc.w = fmaf(a, hv.w, acc.w);
            }
        }
    }

    acc.x += __shfl_xor_sync(0xffffffffu, acc.x, 16);
    acc.y += __shfl_xor_sync(0xffffffffu, acc.y, 16);
    acc.z += __shfl_xor_sync(0xffffffffu, acc.z, 16);
    acc.w += __shfl_xor_sync(0xffffffffu, acc.w, 16);

    float4 b4 = __ldg(&((const float4*)bias)[q]);
    float4 v;
    v.x = acc.x + b4.x; v.y = acc.y + b4.y;
    v.z = acc.z + b4.z; v.w = acc.w + b4.w;
    float dot = v.x * v.x + v.y * v.y + v.z * v.z + v.w * v.w;
    float ss = wsum(dot) * 0.5f;
    float inv = 1.0f / fmaxf(sqrtf(ss), 1e-12f);
    float4 o;
    o.x = fmaxf(v.x * inv, 0.0f);
    o.y = fmaxf(v.y * inv, 0.0f);
    o.z = fmaxf(v.z * inv, 0.0f);
    o.w = fmaxf(v.w * inv, 0.0f);
    return o;
}

// ---------------- K2a: agg + fused next-layer GEMM epilogue ----------------
// 8 warps/block; W staged in smem; per-warp row buffer for the epilogue.
__global__ __launch_bounds__(256) void k_agg_fused(
        const float* __restrict__ hin, const float* __restrict__ asin,
        const float* __restrict__ adin, const float* __restrict__ bias,
        const float* __restrict__ w, const float* __restrict__ a_src,
        const float* __restrict__ a_dst,
        float* __restrict__ hout, float* __restrict__ asout,
        float* __restrict__ adout) {
    __shared__ float ws[DIM * DIM];   // 16 KB (next-layer W)
    __shared__ float buf[8][DIM];     // 2 KB per-warp row
    int tid = threadIdx.x;
    {
        const float4* w4 = (const float4*)w;
        float4* ws4 = (float4*)ws;
#pragma unroll
        for (int k = tid; k < DIM * DIM / 4; k += 256) ws4[k] = w4[k];
    }
    __syncthreads();

    int wid = tid >> 5;
    int lane = tid & 31;
    int i = blockIdx.x * 8 + wid;
    if (i >= NN) return;
    int sub = lane >> 4;
    int q = lane & 15;

    float4 o = agg_core(i, lane, sub, q, hin, asin, adin[i], bias);

    // epilogue: h_next = row @ W, as/ad scalars
    if (sub == 0) {
        buf[wid][4 * q + 0] = o.x;
        buf[wid][4 * q + 1] = o.y;
        buf[wid][4 * q + 2] = o.z;
        buf[wid][4 * q + 3] = o.w;
    }
    __syncwarp();

    float h0 = 0.0f, h1 = 0.0f;
#pragma unroll
    for (int k = 0; k < DIM; k++) {
        float xv = buf[wid][k];
        h0 = fmaf(xv, ws[k * DIM + lane], h0);
        h1 = fmaf(xv, ws[k * DIM + lane + 32], h1);
    }
    float r1 = wsum(h0 * __ldg(&a_src[lane]) + h1 * __ldg(&a_src[lane + 32]));
    float r2 = wsum(h0 * __ldg(&a_dst[lane]) + h1 * __ldg(&a_dst[lane + 32]));
    hout[i * DIM + lane] = h0;
    hout[i * DIM + lane + 32] = h1;
    if (lane == 0) { asout[i] = r1; adout[i] = r2; }
}

// ---------------- K2b: final agg (layer 3) -> g_fin ----------------
__global__ __launch_bounds__(256) void k_agg_last(
        const float* __restrict__ hin, const float* __restrict__ asin,
        const float* __restrict__ adin, const float* __restrict__ bias) {
    int i = blockIdx.x * 8 + (threadIdx.x >> 5);
    int lane = threadIdx.x & 31;
    if (i >= NN) return;
    int sub = lane >> 4;
    int q = lane & 15;
    float4 o = agg_core(i, lane, sub, q, hin, asin, adin[i], bias);
    if (sub == 0) ((float4*)g_fin)[(long)i * 16 + q] = o;
}

// ---------------- fused pool + MLP head + log_softmax ----------------
__device__ __forceinline__ int lbound(const void* batch, long long key) {
    int lo = 0, hi = NN;
    while (lo < hi) {
        int m = (lo + hi) >> 1;
        if (load_batch(batch, m) < key) lo = m + 1; else hi = m;
    }
    return lo;
}

__global__ __launch_bounds__(256) void k_head(
        const void* __restrict__ batch,
        const float* __restrict__ fc1_w, const float* __restrict__ fc1_b,
        const float* __restrict__ fc2_w, const float* __restrict__ fc2_b,
        float* __restrict__ out) {
    __shared__ float part[4][DIM];
    __shared__ float gv[DIM];
    __shared__ float a1s[DIM];
    __shared__ float lg[CC];
    __shared__ float m_s, lse_s;
    int b = blockIdx.x;
    int tid = threadIdx.x;
    int c = tid >> 6;
    int t = tid & 63;

    int lo = lbound(batch, b);
    int hi = lbound(batch, b + 1);
    float acc = 0.0f;
    for (int n = lo + c; n < hi; n += 4) acc += g_fin[n * DIM + t];
    part[c][t] = acc;
    __syncthreads();

    if (tid < DIM) gv[t] = part[0][t] + part[1][t] + part[2][t] + part[3][t];
    __syncthreads();

    if (tid < DIM) {
        float a = fc1_b[t];
#pragma unroll
        for (int k = 0; k < DIM; k++) a = fmaf(gv[k], fc1_w[k * DIM + t], a);
        a1s[t] = fmaxf(a, 0.0f);
    }
    __syncthreads();

    if (tid < CC) {
        float l = fc2_b[tid];
#pragma unroll
        for (int k = 0; k < DIM; k++) l = fmaf(a1s[k], fc2_w[k * CC + tid], l);
        lg[tid] = l;
    }
    __syncthreads();
    if (tid == 0) {
        float m = lg[0];
#pragma unroll
        for (int cc = 1; cc < CC; cc++) m = fmaxf(m, lg[cc]);
        float se = 0.0f;
#pragma unroll
        for (int cc = 0; cc < CC; cc++) se += expf(lg[cc] - m);
        m_s = m;
        lse_s = logf(se);
    }
    __syncthreads();
    if (tid < CC) out[b * CC + tid] = lg[tid] - m_s - lse_s;
}

// ---------------- launch ----------------
extern "C" void kernel_launch(void* const* d_in, const int* in_sizes, int n_in,
                              void* d_out, int out_size) {
    const float* x     = (const float*)d_in[0];
    const void*  ei    = d_in[1];
    const void*  batch = d_in[2];
    const float* w1  = (const float*)d_in[3];
    const float* as1 = (const float*)d_in[4];
    const float* ad1 = (const float*)d_in[5];
    const float* b1  = (const float*)d_in[6];
    const float* w2  = (const float*)d_in[7];
    const float* as2 = (const float*)d_in[8];
    const float* ad2 = (const float*)d_in[9];
    const float* b2  = (const float*)d_in[10];
    const float* w3  = (const float*)d_in[11];
    const float* as3 = (const float*)d_in[12];
    const float* ad3 = (const float*)d_in[13];
    const float* b3  = (const float*)d_in[14];
    const float* fc1_w = (const float*)d_in[15];
    const float* fc1_b = (const float*)d_in[16];
    const float* fc2_w = (const float*)d_in[17];
    const float* fc2_b = (const float*)d_in[18];
    float* out = (float*)d_out;

    float *hA, *hB, *asA, *adA, *asB, *adB;
    void *degp, *wcntp;
    cudaGetSymbolAddress((void**)&hA, g_hA);
    cudaGetSymbolAddress((void**)&hB, g_hB);
    cudaGetSymbolAddress((void**)&asA, g_asA);
    cudaGetSymbolAddress((void**)&adA, g_adA);
    cudaGetSymbolAddress((void**)&asB, g_asB);
    cudaGetSymbolAddress((void**)&adB, g_adB);
    cudaGetSymbolAddress(&degp, g_deg);
    cudaGetSymbolAddress(&wcntp, g_wcnt);

    static cudaStream_t s_aux = nullptr;
    static cudaEvent_t s_evF = nullptr, s_evJ = nullptr;
    if (!s_aux) {
        cudaStreamCreateWithFlags(&s_aux, cudaStreamNonBlocking);
        cudaEventCreateWithFlags(&s_evF, cudaEventDisableTiming);
        cudaEventCreateWithFlags(&s_evJ, cudaEventDisableTiming);
    }

    const int EB = 256;
    const int egrid = (ET + EB - 1) / EB;
    const int ggrid = (NN + 31) / 32;
    const int agrid = (NN + 7) / 8;

    // fork: layer-1 GEMM is independent of CSR build and dtype detection
    cudaEventRecord(s_evF, 0);
    cudaStreamWaitEvent(s_aux, s_evF, 0);
    k_gemm_attn<<<ggrid, 256, 0, s_aux>>>(x, w1, as1, ad1, hA, asA, adA);
    cudaEventRecord(s_evJ, s_aux);

    // CSR build on main stream
    k_detect<<<1, 32>>>(ei);
    cudaMemsetAsync(degp, 0, NN * sizeof(int), 0);
    cudaMemsetAsync(wcntp, 0, NN * sizeof(int), 0);
    k_hist<<<egrid, EB>>>(ei);
    k_scan_block<<<NB, 256>>>();
    k_scan_fix<<<NB, 256>>>();
    k_scatter<<<egrid, EB>>>(ei);

    // join, then the three layers (gemm of layers 2/3 fused into agg epilogues)
    cudaStreamWaitEvent((cudaStream_t)0, s_evJ, 0);
    k_agg_fused<<<agrid, 256>>>(hA, asA, adA, b1, w2, as2, ad2, hB, asB, adB);
    k_agg_fused<<<agrid, 256>>>(hB, asB, adB, b2, w3, as3, ad3, hA, asA, adA);
    k_agg_last<<<agrid, 256>>>(hA, asA, adA, b3);

    // fused pool + head
    k_head<<<GG, 256>>>(batch, fc1_w, fc1_b, fc2_w, fc2_b, out);
}

// round 7
// speedup vs baseline: 1.0756x; 1.0756x over previous
#include <cuda_runtime.h>
#include <math.h>

#define NN 50000
#define EE 800000
#define ET (EE + NN)   // edges + self loops
#define DIM 64
#define GG 256
#define CC 10
#define NEG_SLOPE 0.2f
#define NB ((NN + 255) / 256)     // scan blocks = 196
#define GGRID ((NN + 31) / 32)    // gemm blocks = 1563
#define EGRID ((ET + 255) / 256)  // edge blocks = 3321

// ---------------- device scratch (static, no allocation) ----------------
__device__ float g_h[NN * DIM];      // h = x @ W  (current layer)
__device__ float g_out[NN * DIM];    // aggregated output / next-layer input
__device__ float g_as[NN];
__device__ float g_ad[NN];

// CSR (built once per launch, reused by all 3 layers)
__device__ int g_deg[NN];
__device__ int g_wcnt[NN];
__device__ int g_row[NN + 1];
__device__ int g_bsum[NB];
__device__ int g_esrc[ET];

// ---------------- helpers ----------------
__device__ __forceinline__ float wsum(float v) {
#pragma unroll
    for (int o = 16; o; o >>= 1) v += __shfl_xor_sync(0xffffffffu, v, o);
    return v;
}
__device__ __forceinline__ float wmax(float v) {
#pragma unroll
    for (int o = 16; o; o >>= 1) v = fmaxf(v, __shfl_xor_sync(0xffffffffu, v, o));
    return v;
}
__device__ __forceinline__ int iwsum(int v) {
#pragma unroll
    for (int o = 16; o; o >>= 1) v += __shfl_xor_sync(0xffffffffu, v, o);
    return v;
}

// inline dtype detection: int64 edge values < 2^31 -> odd 32-bit words are 0.
// For int32 data these words are 8 independent random node ids (~0 chance all zero).
__device__ __forceinline__ bool edge_is64(const void* ei) {
    const int* p = (const int*)ei;
    int acc = p[1] | p[3] | p[5] | p[7] | p[9] | p[11] | p[13] | p[15];
    return acc == 0;
}

__device__ __forceinline__ void load_edge(const void* ei, bool is64, int e, int& s, int& d) {
    if (e >= EE) { s = d = e - EE; return; }  // self loop
    if (is64) {
        const long long* p = (const long long*)ei;
        s = (int)p[e];
        d = (int)p[EE + e];
    } else {
        const int* p = (const int*)ei;
        s = p[e];
        d = p[EE + e];
    }
}

__device__ __forceinline__ long long load_batch(const void* batch, bool is64, int n) {
    return is64 ? ((const long long*)batch)[n]
                : (long long)((const int*)batch)[n];
}

// ---------------- K1: combined hist (CSR) + layer-1 GEMM ----------------
// blocks [0, GGRID): gemm1 on 32 nodes each; blocks [GGRID, GGRID+EGRID): hist.
// The two halves are independent and co-schedule on the same wave.
__global__ __launch_bounds__(256) void k_hist_gemm(
        const void* __restrict__ ei,
        const float* __restrict__ xin, const float* __restrict__ w,
        const float* __restrict__ a_src, const float* __restrict__ a_dst) {
    __shared__ float ws[DIM * DIM];          // 16 KB
    __shared__ float xr[32][DIM];            // 8 KB
    __shared__ float pr1a[32], pr1b[32], pr2a[32], pr2b[32];
    int tid = threadIdx.x;

    if (blockIdx.x >= GGRID) {
        // ---- hist part ----
        int e = (blockIdx.x - GGRID) * 256 + tid;
        if (e < ET) {
            bool is64 = edge_is64(ei);
            int s, d;
            load_edge(ei, is64, e, s, d);
            atomicAdd(&g_deg[d], 1);
        }
        return;
    }

    // ---- gemm1 part ----
    int base = blockIdx.x * 32;
    {
        const float4* w4 = (const float4*)w;
        float4* ws4 = (float4*)ws;
#pragma unroll
        for (int k = tid; k < DIM * DIM / 4; k += 256) ws4[k] = w4[k];
    }
    {
        const float4* x4 = (const float4*)xin;
        float4* xr4 = (float4*)&xr[0][0];
#pragma unroll
        for (int k = tid; k < 32 * DIM / 4; k += 256) {
            int row = k >> 4;
            float4 v = make_float4(0.f, 0.f, 0.f, 0.f);
            if (base + row < NN) v = x4[(long)(base + row) * 16 + (k & 15)];
            xr4[k] = v;
        }
    }
    __syncthreads();

    int t = tid & 63;
    int grp = tid >> 6;
    int wsel = (tid >> 5) & 1;
    float as_t = __ldg(&a_src[t]);
    float ad_t = __ldg(&a_dst[t]);

#pragma unroll
    for (int r = grp; r < 32; r += 4) {
        int i = base + r;
        float h = 0.0f;
#pragma unroll
        for (int k = 0; k < DIM; k++) h = fmaf(xr[r][k], ws[k * DIM + t], h);
        float r1 = wsum(h * as_t);
        float r2 = wsum(h * ad_t);
        if ((tid & 31) == 0) {
            if (wsel == 0) { pr1a[r] = r1; pr2a[r] = r2; }
            else           { pr1b[r] = r1; pr2b[r] = r2; }
        }
        if (i < NN) g_h[i * DIM + t] = h;
    }
    __syncthreads();
    if (tid < 32 && base + tid < NN) {
        g_as[base + tid] = pr1a[tid] + pr1b[tid];
        g_ad[base + tid] = pr2a[tid] + pr2b[tid];
    }
}

// ---------------- standalone GEMM (layers 2, 3) ----------------
__global__ __launch_bounds__(256) void k_gemm_attn(
        const float* __restrict__ xin, const float* __restrict__ w,
        const float* __restrict__ a_src, const float* __restrict__ a_dst) {
    __shared__ float ws[DIM * DIM];
    __shared__ float xr[32][DIM];
    __shared__ float pr1a[32], pr1b[32], pr2a[32], pr2b[32];
    int tid = threadIdx.x;
    int base = blockIdx.x * 32;

    {
        const float4* w4 = (const float4*)w;
        float4* ws4 = (float4*)ws;
#pragma unroll
        for (int k = tid; k < DIM * DIM / 4; k += 256) ws4[k] = w4[k];
    }
    {
        const float4* x4 = (const float4*)xin;
        float4* xr4 = (float4*)&xr[0][0];
#pragma unroll
        for (int k = tid; k < 32 * DIM / 4; k += 256) {
            int row = k >> 4;
            float4 v = make_float4(0.f, 0.f, 0.f, 0.f);
            if (base + row < NN) v = x4[(long)(base + row) * 16 + (k & 15)];
            xr4[k] = v;
        }
    }
    __syncthreads();

    int t = tid & 63;
    int grp = tid >> 6;
    int wsel = (tid >> 5) & 1;
    float as_t = __ldg(&a_src[t]);
    float ad_t = __ldg(&a_dst[t]);

#pragma unroll
    for (int r = grp; r < 32; r += 4) {
        int i = base + r;
        float h = 0.0f;
#pragma unroll
        for (int k = 0; k < DIM; k++) h = fmaf(xr[r][k], ws[k * DIM + t], h);
        float r1 = wsum(h * as_t);
        float r2 = wsum(h * ad_t);
        if ((tid & 31) == 0) {
            if (wsel == 0) { pr1a[r] = r1; pr2a[r] = r2; }
            else           { pr1b[r] = r1; pr2b[r] = r2; }
        }
        if (i < NN) g_h[i * DIM + t] = h;
    }
    __syncthreads();
    if (tid < 32 && base + tid < NN) {
        g_as[base + tid] = pr1a[tid] + pr1b[tid];
        g_ad[base + tid] = pr2a[tid] + pr2b[tid];
    }
}

// ---------------- CSR scan + scatter ----------------
__global__ void k_scan_block() {
    __shared__ int sm[256];
    int t = threadIdx.x;
    int i = blockIdx.x * 256 + t;
    int v = (i < NN) ? g_deg[i] : 0;
    sm[t] = v;
    __syncthreads();
#pragma unroll
    for (int off = 1; off < 256; off <<= 1) {
        int tmp = (t >= off) ? sm[t - off] : 0;
        __syncthreads();
        sm[t] += tmp;
        __syncthreads();
    }
    if (i < NN) g_row[i] = sm[t] - v;   // exclusive within block
    if (t == 255) g_bsum[blockIdx.x] = sm[255];
}

__global__ void k_scan_fix() {
    __shared__ int wred[8];
    __shared__ int s_off;
    int t = threadIdx.x;
    int v = (t < blockIdx.x && t < NB) ? g_bsum[t] : 0;
    v = iwsum(v);
    if ((t & 31) == 0) wred[t >> 5] = v;
    __syncthreads();
    if (t == 0) {
        int o = 0;
#pragma unroll
        for (int k = 0; k < 8; k++) o += wred[k];
        s_off = o;
    }
    __syncthreads();
    int i = blockIdx.x * 256 + t;
    if (i < NN) g_row[i] += s_off;
    if (blockIdx.x == 0 && t == 0) g_row[NN] = ET;
}

__global__ void k_scatter(const void* __restrict__ ei) {
    int e = blockIdx.x * blockDim.x + threadIdx.x;
    if (e >= ET) return;
    bool is64 = edge_is64(ei);
    int s, d;
    load_edge(ei, is64, e, s, d);
    int pos = g_row[d] + atomicAdd(&g_wcnt[d], 1);
    g_esrc[pos] = s;
}

// ---------------- K2: fused softmax + aggregate + bias + l2norm + relu ----------------
__global__ __launch_bounds__(256) void k_node_agg(const float* __restrict__ bias) {
    int i = blockIdx.x * 8 + (threadIdx.x >> 5);
    int lane = threadIdx.x & 31;
    if (i >= NN) return;
    int sub = lane >> 4;
    int q = lane & 15;
    int beg = g_row[i];
    int end = g_row[i + 1];
    int deg = end - beg;
    float ad_i = g_ad[i];
    const float4* h4 = (const float4*)g_h;
    float4 acc = make_float4(0.f, 0.f, 0.f, 0.f);

    if (deg <= 32) {
        int s_l = 0;
        float e_l = -1e30f;
        if (lane < deg) {
            s_l = g_esrc[beg + lane];
            float v = g_as[s_l] + ad_i;
            e_l = (v > 0.0f) ? v : NEG_SLOPE * v;
        }
        float emax = wmax(e_l);
        float ex = (lane < deg) ? __expf(e_l - emax) : 0.0f;
        float denom = wsum(ex) + 1e-16f;
        float alpha_l = ex / denom;
#pragma unroll 4
        for (int k = 0; k < deg; k += 2) {
            int kk = k + sub;
            float a = __shfl_sync(0xffffffffu, alpha_l, kk);
            int s = __shfl_sync(0xffffffffu, s_l, kk);
            float4 hv = __ldg(&h4[(long)s * 16 + q]);
            acc.x = fmaf(a, hv.x, acc.x);
            acc.y = fmaf(a, hv.y, acc.y);
            acc.z = fmaf(a, hv.z, acc.z);
            acc.w = fmaf(a, hv.w, acc.w);
        }
    } else {
        float emax = -1e30f;
        for (int j = beg + lane; j < end; j += 32) {
            int s = g_esrc[j];
            float v = g_as[s] + ad_i;
            v = (v > 0.0f) ? v : NEG_SLOPE * v;
            emax = fmaxf(emax, v);
        }
        emax = wmax(emax);
        float dsum = 0.0f;
        for (int j = beg + lane; j < end; j += 32) {
            int s = g_esrc[j];
            float v = g_as[s] + ad_i;
            v = (v > 0.0f) ? v : NEG_SLOPE * v;
            dsum += __expf(v - emax);
        }
        float denom = wsum(dsum) + 1e-16f;
        for (int cbase = beg; cbase < end; cbase += 32) {
            int j = cbase + lane;
            int s_l = 0;
            float alpha_l = 0.0f;
            if (j < end) {
                s_l = g_esrc[j];
                float v = g_as[s_l] + ad_i;
                v = (v > 0.0f) ? v : NEG_SLOPE * v;
                alpha_l = __expf(v - emax) / denom;
            }
            int cnt = min(32, end - cbase);
#pragma unroll 4
            for (int k = 0; k < cnt; k += 2) {
                int kk = k + sub;
                float a = __shfl_sync(0xffffffffu, alpha_l, kk);
                int s = __shfl_sync(0xffffffffu, s_l, kk);
                float4 hv = __ldg(&h4[(long)s * 16 + q]);
                acc.x = fmaf(a, hv.x, acc.x);
                acc.y = fmaf(a, hv.y, acc.y);
                acc.z = fmaf(a, hv.z, acc.z);
                acc.w = fmaf(a, hv.w, acc.w);
            }
        }
    }

    acc.x += __shfl_xor_sync(0xffffffffu, acc.x, 16);
    acc.y += __shfl_xor_sync(0xffffffffu, acc.y, 16);
    acc.z += __shfl_xor_sync(0xffffffffu, acc.z, 16);
    acc.w += __shfl_xor_sync(0xffffffffu, acc.w, 16);

    float4 b4 = __ldg(&((const float4*)bias)[q]);
    float4 v;
    v.x = acc.x + b4.x; v.y = acc.y + b4.y;
    v.z = acc.z + b4.z; v.w = acc.w + b4.w;
    float dot = v.x * v.x + v.y * v.y + v.z * v.z + v.w * v.w;
    float ss = wsum(dot) * 0.5f;
    float inv = 1.0f / fmaxf(sqrtf(ss), 1e-12f);
    if (sub == 0) {
        float4 o;
        o.x = fmaxf(v.x * inv, 0.0f);
        o.y = fmaxf(v.y * inv, 0.0f);
        o.z = fmaxf(v.z * inv, 0.0f);
        o.w = fmaxf(v.w * inv, 0.0f);
        ((float4*)g_out)[(long)i * 16 + q] = o;
    }
}

// ---------------- fused pool + MLP head + log_softmax ----------------
__device__ __forceinline__ int lbound(const void* batch, bool is64, long long key) {
    int lo = 0, hi = NN;
    while (lo < hi) {
        int m = (lo + hi) >> 1;
        if (load_batch(batch, is64, m) < key) lo = m + 1; else hi = m;
    }
    return lo;
}

__global__ __launch_bounds__(256) void k_head(
        const void* __restrict__ ei, const void* __restrict__ batch,
        const float* __restrict__ fc1_w, const float* __restrict__ fc1_b,
        const float* __restrict__ fc2_w, const float* __restrict__ fc2_b,
        float* __restrict__ out) {
    __shared__ float part[4][DIM];
    __shared__ float gv[DIM];
    __shared__ float a1s[DIM];
    __shared__ float lg[CC];
    __shared__ float m_s, lse_s;
    int b = blockIdx.x;
    int tid = threadIdx.x;
    int c = tid >> 6;
    int t = tid & 63;
    bool is64 = edge_is64(ei);

    int lo = lbound(batch, is64, b);
    int hi = lbound(batch, is64, b + 1);
    float acc = 0.0f;
    for (int n = lo + c; n < hi; n += 4) acc += g_out[n * DIM + t];
    part[c][t] = acc;
    __syncthreads();

    if (tid < DIM) gv[t] = part[0][t] + part[1][t] + part[2][t] + part[3][t];
    __syncthreads();

    if (tid < DIM) {
        float a = fc1_b[t];
#pragma unroll
        for (int k = 0; k < DIM; k++) a = fmaf(gv[k], fc1_w[k * DIM + t], a);
        a1s[t] = fmaxf(a, 0.0f);
    }
    __syncthreads();

    if (tid < CC) {
        float l = fc2_b[tid];
#pragma unroll
        for (int k = 0; k < DIM; k++) l = fmaf(a1s[k], fc2_w[k * CC + tid], l);
        lg[tid] = l;
    }
    __syncthreads();
    if (tid == 0) {
        float m = lg[0];
#pragma unroll
        for (int cc = 1; cc < CC; cc++) m = fmaxf(m, lg[cc]);
        float se = 0.0f;
#pragma unroll
        for (int cc = 0; cc < CC; cc++) se += expf(lg[cc] - m);
        m_s = m;
        lse_s = logf(se);
    }
    __syncthreads();
    if (tid < CC) out[b * CC + tid] = lg[tid] - m_s - lse_s;
}

// ---------------- launch ----------------
extern "C" void kernel_launch(void* const* d_in, const int* in_sizes, int n_in,
                              void* d_out, int out_size) {
    const float* x     = (const float*)d_in[0];
    const void*  ei    = d_in[1];
    const void*  batch = d_in[2];
    const float* w1  = (const float*)d_in[3];
    const float* as1 = (const float*)d_in[4];
    const float* ad1 = (const float*)d_in[5];
    const float* b1  = (const float*)d_in[6];
    const float* w2  = (const float*)d_in[7];
    const float* as2 = (const float*)d_in[8];
    const float* ad2 = (const float*)d_in[9];
    const float* b2  = (const float*)d_in[10];
    const float* w3  = (const float*)d_in[11];
    const float* as3 = (const float*)d_in[12];
    const float* ad3 = (const float*)d_in[13];
    const float* b3  = (const float*)d_in[14];
    const float* fc1_w = (const float*)d_in[15];
    const float* fc1_b = (const float*)d_in[16];
    const float* fc2_w = (const float*)d_in[17];
    const float* fc2_b = (const float*)d_in[18];
    float* out = (float*)d_out;

    float* g_out_ptr = nullptr;
    void* degp = nullptr;
    void* wcntp = nullptr;
    cudaGetSymbolAddress((void**)&g_out_ptr, g_out);
    cudaGetSymbolAddress(&degp, g_deg);
    cudaGetSymbolAddress(&wcntp, g_wcnt);

    const int agrid = (NN + 7) / 8;

    // zero counters (memset nodes are cheap in a graph)
    cudaMemsetAsync(degp, 0, NN * sizeof(int), 0);
    cudaMemsetAsync(wcntp, 0, NN * sizeof(int), 0);

    // combined: layer-1 GEMM + CSR histogram in one grid (independent halves)
    k_hist_gemm<<<GGRID + EGRID, 256>>>(ei, x, w1, as1, ad1);

    // CSR scan + scatter
    k_scan_block<<<NB, 256>>>();
    k_scan_fix<<<NB, 256>>>();
    k_scatter<<<EGRID, 256>>>(ei);

    // layer 1 aggregation
    k_node_agg<<<agrid, 256>>>(b1);
    // layer 2
    k_gemm_attn<<<GGRID, 256>>>(g_out_ptr, w2, as2, ad2);
    k_node_agg<<<agrid, 256>>>(b2);
    // layer 3
    k_gemm_attn<<<GGRID, 256>>>(g_out_ptr, w3, as3, ad3);
    k_node_agg<<<agrid, 256>>>(b3);

    // fused pool + head
    k_head<<<GG, 256>>>(ei, batch, fc1_w, fc1_b, fc2_w, fc2_b, out);
}